// round 1
// baseline (speedup 1.0000x reference)
#include <cuda_runtime.h>
#include <math.h>

#define BATCH 8
#define CHAN  128
#define HDIM  64
#define WDIM  64
#define LLEN  4096           // HDIM*WDIM
#define NHEAD 8
#define NPTS  8
#define DHEAD 16

// Scratch (no cudaMalloc allowed)
__device__ float g_value[BATCH * LLEN * CHAN];          // [b][l][c] (c = head*16+d)
__device__ float g_off  [BATCH * LLEN * NHEAD * NPTS * 2];
__device__ float g_attn [BATCH * LLEN * NHEAD * NPTS];  // raw logits
__device__ float g_mid  [BATCH * LLEN * CHAN];

// ---------------------------------------------------------------------------
// Kernel 1: fused projections.
//   value[b,l,0:128] = nbr[b,:,l] @ W_val + b_val
//   off  [b,l,0:128] = 10*tanh(ext[b,:,l] @ W_off + b_off)
//   attn [b,l,0:64]  = ext[b,:,l] @ W_attn + b_attn   (softmax deferred)
// Tile: 64 l-rows x 320 out-cols, 256 threads (16x16), 4x20 accum per thread.
// ---------------------------------------------------------------------------
__global__ __launch_bounds__(256, 2)
void proj_kernel(const float* __restrict__ nbr, const float* __restrict__ ext,
                 const float* __restrict__ Wv, const float* __restrict__ bv,
                 const float* __restrict__ Wo, const float* __restrict__ bo,
                 const float* __restrict__ Wa, const float* __restrict__ ba)
{
    __shared__ float As_n[8][64];
    __shared__ float As_e[8][64];
    __shared__ float Bs[8][320];

    const int b  = blockIdx.y;
    const int l0 = blockIdx.x * 64;
    const int tid = threadIdx.x;
    const int tx = tid & 15;       // out-col group
    const int ty = tid >> 4;       // l-row group

    float acc[4][20];
    #pragma unroll
    for (int i = 0; i < 4; i++)
        #pragma unroll
        for (int j = 0; j < 20; j++) acc[i][j] = 0.f;

    for (int k0 = 0; k0 < CHAN; k0 += 8) {
        // A tiles: [8 k][64 l], coalesced along l
        #pragma unroll
        for (int i = 0; i < 2; i++) {
            int idx = tid + i * 256;
            int r = idx >> 6, cl = idx & 63;
            As_n[r][cl] = nbr[(size_t)(b * CHAN + k0 + r) * LLEN + l0 + cl];
            As_e[r][cl] = ext[(size_t)(b * CHAN + k0 + r) * LLEN + l0 + cl];
        }
        // B tile: [8 k][320 n] = [W_val | W_off | W_attn]
        #pragma unroll
        for (int i = 0; i < 10; i++) {
            int idx = tid + i * 256;
            int r = idx / 320, n = idx - r * 320;
            float v;
            if (n < 128)      v = Wv[(k0 + r) * 128 + n];
            else if (n < 256) v = Wo[(k0 + r) * 128 + (n - 128)];
            else              v = Wa[(k0 + r) * 64  + (n - 256)];
            Bs[r][n] = v;
        }
        __syncthreads();

        #pragma unroll
        for (int kk = 0; kk < 8; kk++) {
            float an[4], ae[4];
            #pragma unroll
            for (int i = 0; i < 4; i++) {
                an[i] = As_n[kk][ty + 16 * i];
                ae[i] = As_e[kk][ty + 16 * i];
            }
            #pragma unroll
            for (int j = 0; j < 20; j++) {
                float bb = Bs[kk][tx + 16 * j];
                #pragma unroll
                for (int i = 0; i < 4; i++)
                    acc[i][j] = fmaf((j < 8 ? an[i] : ae[i]), bb, acc[i][j]);
            }
        }
        __syncthreads();
    }

    // Epilogue
    #pragma unroll
    for (int i = 0; i < 4; i++) {
        int l = l0 + ty + 16 * i;
        size_t row = (size_t)(b * LLEN + l);
        #pragma unroll
        for (int j = 0; j < 20; j++) {
            int n = tx + 16 * j;
            if (n < 128) {
                g_value[row * 128 + n] = acc[i][j] + bv[n];
            } else if (n < 256) {
                int m = n - 128;
                g_off[row * 128 + m] = 10.0f * tanhf(acc[i][j] + bo[m]);
            } else {
                int m = n - 256;
                g_attn[row * 64 + m] = acc[i][j] + ba[m];
            }
        }
    }
}

// ---------------------------------------------------------------------------
// Kernel 2: softmax + bilinear sampling + attention-weighted sum.
// One 128-thread block per (b,l). Thread t = (head = t>>4, d = t&15).
// px = x + off_x, py = y + off_y   (derivation: ref*(W)-0.5 cancels the +0.5)
// ---------------------------------------------------------------------------
__global__ __launch_bounds__(128)
void sample_kernel()
{
    const int bl = blockIdx.x;           // b*LLEN + l
    const int l  = bl & (LLEN - 1);
    const int t  = threadIdx.x;

    __shared__ float offs[128];
    __shared__ float logit[64];
    offs[t] = g_off[(size_t)bl * 128 + t];
    if (t < 64) logit[t] = g_attn[(size_t)bl * 64 + t];
    __syncthreads();

    const int head = t >> 4;
    const int d    = t & 15;

    // softmax over the head's 8 points (redundant across the 16 d-lanes; cheap)
    float m = -1e30f;
    #pragma unroll
    for (int p = 0; p < 8; p++) m = fmaxf(m, logit[head * 8 + p]);
    float e[8], s = 0.f;
    #pragma unroll
    for (int p = 0; p < 8; p++) { e[p] = __expf(logit[head * 8 + p] - m); s += e[p]; }
    const float inv = 1.0f / s;

    const float xb = (float)(l & (WDIM - 1));
    const float yb = (float)(l >> 6);
    const float* vbase = g_value + (size_t)(bl >> 12) * LLEN * CHAN + head * DHEAD + d;

    float acc = 0.f;
    #pragma unroll
    for (int p = 0; p < 8; p++) {
        float px = xb + offs[(head * 8 + p) * 2];
        float py = yb + offs[(head * 8 + p) * 2 + 1];
        float x0f = floorf(px), y0f = floorf(py);
        float fx = px - x0f, fy = py - y0f;
        int x0 = (int)x0f, y0 = (int)y0f;

        bool xv0 = (x0 >= 0)  & (x0 < WDIM);
        bool xv1 = (x0 >= -1) & (x0 < WDIM - 1);
        bool yv0 = (y0 >= 0)  & (y0 < HDIM);
        bool yv1 = (y0 >= -1) & (y0 < HDIM - 1);

        float v00 = 0.f, v10 = 0.f, v01 = 0.f, v11 = 0.f;
        if (yv0) {
            int r = y0 * WDIM;
            if (xv0) v00 = vbase[(size_t)(r + x0)     * CHAN];
            if (xv1) v10 = vbase[(size_t)(r + x0 + 1) * CHAN];
        }
        if (yv1) {
            int r = (y0 + 1) * WDIM;
            if (xv0) v01 = vbase[(size_t)(r + x0)     * CHAN];
            if (xv1) v11 = vbase[(size_t)(r + x0 + 1) * CHAN];
        }
        float gx0 = 1.f - fx, gy0 = 1.f - fy;
        float bil = v00 * gx0 * gy0 + v10 * fx * gy0 + v01 * gx0 * fy + v11 * fx * fy;
        acc = fmaf(e[p] * inv, bil, acc);
    }
    g_mid[(size_t)bl * 128 + t] = acc;
}

// ---------------------------------------------------------------------------
// Kernel 3: output projection with transposed store.
//   out[b, n, l] = sum_k mid[b, l, k] * W_out[k, n] + b_out[n]
// Tile: 128 n x 64 l, 256 threads (tx->l for coalesced stores, ty->n).
// ---------------------------------------------------------------------------
__global__ __launch_bounds__(256, 2)
void out_kernel(const float* __restrict__ Wout, const float* __restrict__ bout,
                float* __restrict__ out)
{
    __shared__ float As[64][9];       // [l][k], padded (gcd(9,32)=1)
    __shared__ float Bs[8][128];      // [k][n]

    const int b  = blockIdx.y;
    const int l0 = blockIdx.x * 64;
    const int tid = threadIdx.x;
    const int tx = tid & 15;          // l group
    const int ty = tid >> 4;          // n group

    float acc[8][4];
    #pragma unroll
    for (int i = 0; i < 8; i++)
        #pragma unroll
        for (int j = 0; j < 4; j++) acc[i][j] = 0.f;

    for (int k0 = 0; k0 < CHAN; k0 += 8) {
        #pragma unroll
        for (int i = 0; i < 2; i++) {
            int idx = tid + i * 256;
            int row = idx >> 3, col = idx & 7;
            As[row][col] = g_mid[(size_t)(b * LLEN + l0 + row) * 128 + k0 + col];
        }
        #pragma unroll
        for (int i = 0; i < 4; i++) {
            int idx = tid + i * 256;
            int r = idx >> 7, n = idx & 127;
            Bs[r][n] = Wout[(k0 + r) * 128 + n];
        }
        __syncthreads();

        #pragma unroll
        for (int kk = 0; kk < 8; kk++) {
            float a[4], w[8];
            #pragma unroll
            for (int j = 0; j < 4; j++) a[j] = As[tx + 16 * j][kk];
            #pragma unroll
            for (int i = 0; i < 8; i++) w[i] = Bs[kk][ty + 16 * i];
            #pragma unroll
            for (int i = 0; i < 8; i++)
                #pragma unroll
                for (int j = 0; j < 4; j++)
                    acc[i][j] = fmaf(w[i], a[j], acc[i][j]);
        }
        __syncthreads();
    }

    #pragma unroll
    for (int i = 0; i < 8; i++) {
        int n = ty + 16 * i;
        float bb = bout[n];
        #pragma unroll
        for (int j = 0; j < 4; j++) {
            out[((size_t)(b * CHAN + n)) * LLEN + l0 + tx + 16 * j] = acc[i][j] + bb;
        }
    }
}

// ---------------------------------------------------------------------------
extern "C" void kernel_launch(void* const* d_in, const int* in_sizes, int n_in,
                              void* d_out, int out_size)
{
    const float* nbr  = (const float*)d_in[0];
    const float* ext  = (const float*)d_in[1];
    const float* Wv   = (const float*)d_in[2];
    const float* bv   = (const float*)d_in[3];
    const float* Wo   = (const float*)d_in[4];
    const float* bo   = (const float*)d_in[5];
    const float* Wa   = (const float*)d_in[6];
    const float* ba   = (const float*)d_in[7];
    const float* Wout = (const float*)d_in[8];
    const float* bout = (const float*)d_in[9];
    float* out = (float*)d_out;

    dim3 gproj(LLEN / 64, BATCH);
    proj_kernel<<<gproj, 256>>>(nbr, ext, Wv, bv, Wo, bo, Wa, ba);

    sample_kernel<<<BATCH * LLEN, 128>>>();

    dim3 gout(LLEN / 64, BATCH);
    out_kernel<<<gout, 256>>>(Wout, bout, out);
}

// round 2
// speedup vs baseline: 1.5528x; 1.5528x over previous
#include <cuda_runtime.h>
#include <math.h>

#define BATCH 8
#define CHAN  128
#define HDIM  64
#define WDIM  64
#define LLEN  4096           // HDIM*WDIM
#define NHEAD 8
#define NPTS  8
#define DHEAD 16

// Scratch (no cudaMalloc allowed)
__device__ float g_value[BATCH * LLEN * CHAN];          // [b][l][c] (c = head*16+d)
__device__ float g_off  [BATCH * LLEN * NHEAD * NPTS * 2];
__device__ float g_attn [BATCH * LLEN * NHEAD * NPTS];  // raw logits
__device__ float g_mid  [BATCH * LLEN * CHAN];

// ---------------------------------------------------------------------------
// Kernel 1: fused projections, 128l x 64n tile, 256 thr, 8x4 per thread.
// blockIdx.y = n-tile (0,1: W_val/nbr; 2,3: W_off/ext; 4: W_attn/ext)
// ---------------------------------------------------------------------------
__global__ __launch_bounds__(256)
void proj_kernel(const float* __restrict__ nbr, const float* __restrict__ ext,
                 const float* __restrict__ Wv, const float* __restrict__ bv,
                 const float* __restrict__ Wo, const float* __restrict__ bo,
                 const float* __restrict__ Wa, const float* __restrict__ ba)
{
    __shared__ float As[16][128];
    __shared__ float Bs[16][64];

    const int nt  = blockIdx.y;
    const int b   = blockIdx.x >> 5;
    const int l0  = (blockIdx.x & 31) << 7;
    const int tid = threadIdx.x;
    const int tx  = tid & 15;      // -> 4 consecutive n
    const int ty  = tid >> 4;      // -> 8 consecutive l

    const float* Asrc = (nt < 2) ? nbr : ext;
    const float* Bsrc;
    int bstride, bcol;
    if (nt == 0)      { Bsrc = Wv; bstride = 128; bcol = 0;  }
    else if (nt == 1) { Bsrc = Wv; bstride = 128; bcol = 64; }
    else if (nt == 2) { Bsrc = Wo; bstride = 128; bcol = 0;  }
    else if (nt == 3) { Bsrc = Wo; bstride = 128; bcol = 64; }
    else              { Bsrc = Wa; bstride = 64;  bcol = 0;  }

    float acc[8][4];
    #pragma unroll
    for (int i = 0; i < 8; i++)
        #pragma unroll
        for (int j = 0; j < 4; j++) acc[i][j] = 0.f;

    for (int k0 = 0; k0 < CHAN; k0 += 16) {
        #pragma unroll
        for (int i = 0; i < 2; i++) {
            int fid = tid + i * 256;
            int row = fid >> 5, c4 = (fid & 31) << 2;
            *(float4*)&As[row][c4] =
                *(const float4*)&Asrc[(size_t)(b * CHAN + k0 + row) * LLEN + l0 + c4];
        }
        {
            int row = tid >> 4, c4 = (tid & 15) << 2;
            *(float4*)&Bs[row][c4] =
                *(const float4*)&Bsrc[(k0 + row) * bstride + bcol + c4];
        }
        __syncthreads();

        #pragma unroll
        for (int kk = 0; kk < 16; kk++) {
            float4 a0 = *(float4*)&As[kk][ty * 8];
            float4 a1 = *(float4*)&As[kk][ty * 8 + 4];
            float4 bb = *(float4*)&Bs[kk][tx * 4];
            float av[8] = {a0.x, a0.y, a0.z, a0.w, a1.x, a1.y, a1.z, a1.w};
            float bw[4] = {bb.x, bb.y, bb.z, bb.w};
            #pragma unroll
            for (int i = 0; i < 8; i++)
                #pragma unroll
                for (int j = 0; j < 4; j++)
                    acc[i][j] = fmaf(av[i], bw[j], acc[i][j]);
        }
        __syncthreads();
    }

    // Epilogue
    if (nt < 2) {
        int n = nt * 64 + tx * 4;
        float4 bia = *(const float4*)&bv[n];
        #pragma unroll
        for (int i = 0; i < 8; i++) {
            int l = l0 + ty * 8 + i;
            float4 v = {acc[i][0] + bia.x, acc[i][1] + bia.y,
                        acc[i][2] + bia.z, acc[i][3] + bia.w};
            *(float4*)&g_value[(size_t)(b * LLEN + l) * 128 + n] = v;
        }
    } else if (nt < 4) {
        int m = (nt - 2) * 64 + tx * 4;
        float4 bia = *(const float4*)&bo[m];
        #pragma unroll
        for (int i = 0; i < 8; i++) {
            int l = l0 + ty * 8 + i;
            float4 v = {10.0f * tanhf(acc[i][0] + bia.x), 10.0f * tanhf(acc[i][1] + bia.y),
                        10.0f * tanhf(acc[i][2] + bia.z), 10.0f * tanhf(acc[i][3] + bia.w)};
            *(float4*)&g_off[(size_t)(b * LLEN + l) * 128 + m] = v;
        }
    } else {
        int m = tx * 4;
        float4 bia = *(const float4*)&ba[m];
        #pragma unroll
        for (int i = 0; i < 8; i++) {
            int l = l0 + ty * 8 + i;
            float4 v = {acc[i][0] + bia.x, acc[i][1] + bia.y,
                        acc[i][2] + bia.z, acc[i][3] + bia.w};
            *(float4*)&g_attn[(size_t)(b * LLEN + l) * 64 + m] = v;
        }
    }
}

// ---------------------------------------------------------------------------
// Kernel 2: softmax + bilinear sampling. One block per (b, 8x8 spatial tile),
// 256 threads. Phase 1: precompute weights + absolute coords into smem.
// Phase 2: loop 64 positions (2 at a time), gather with heavy L1 reuse.
// ---------------------------------------------------------------------------
__global__ __launch_bounds__(256)
void sample_kernel()
{
    __shared__ float sw [64 * 64];   // [l_loc][h*8+p] softmax weight
    __shared__ float spx[64 * 64];   // absolute sample x
    __shared__ float spy[64 * 64];   // absolute sample y

    const int b    = blockIdx.y;
    const int tile = blockIdx.x;                 // 0..63
    const int x0t  = (tile & 7) * 8;
    const int y0t  = (tile >> 3) * 8;
    const int tid  = threadIdx.x;

    // ---- Phase 1: 512 (l,h) tasks, 2 per thread ----
    #pragma unroll
    for (int i = 0; i < 2; i++) {
        int task  = tid + i * 256;
        int l_loc = task >> 3;
        int h     = task & 7;
        int lx = x0t + (l_loc & 7);
        int ly = y0t + (l_loc >> 3);
        size_t bl = (size_t)b * LLEN + ly * WDIM + lx;

        const float* op = g_off + bl * 128 + h * 16;
        float4 o0 = *(const float4*)(op);
        float4 o1 = *(const float4*)(op + 4);
        float4 o2 = *(const float4*)(op + 8);
        float4 o3 = *(const float4*)(op + 12);
        float ox[8] = {o0.x, o0.z, o1.x, o1.z, o2.x, o2.z, o3.x, o3.z};
        float oy[8] = {o0.y, o0.w, o1.y, o1.w, o2.y, o2.w, o3.y, o3.w};

        const float* ap = g_attn + bl * 64 + h * 8;
        float4 g0 = *(const float4*)(ap);
        float4 g1 = *(const float4*)(ap + 4);
        float lg[8] = {g0.x, g0.y, g0.z, g0.w, g1.x, g1.y, g1.z, g1.w};

        float m = -1e30f;
        #pragma unroll
        for (int p = 0; p < 8; p++) m = fmaxf(m, lg[p]);
        float e[8], s = 0.f;
        #pragma unroll
        for (int p = 0; p < 8; p++) { e[p] = __expf(lg[p] - m); s += e[p]; }
        float inv = 1.0f / s;

        int base = l_loc * 64 + h * 8;
        #pragma unroll
        for (int p = 0; p < 8; p++) {
            sw [base + p] = e[p] * inv;
            spx[base + p] = (float)lx + ox[p];
            spy[base + p] = (float)ly + oy[p];
        }
    }
    __syncthreads();

    // ---- Phase 2 ----
    const int half = tid >> 7;         // 0/1 : which l of the pair
    const int tt   = tid & 127;        // channel c = h*16+d
    const int h    = tt >> 4;
    const float* vbase = g_value + (size_t)b * LLEN * CHAN + tt;

    for (int it = 0; it < 32; it++) {
        int l_loc = it * 2 + half;
        int lx = x0t + (l_loc & 7);
        int ly = y0t + (l_loc >> 3);

        float acc = 0.f;
        #pragma unroll
        for (int p = 0; p < 8; p++) {
            int s = l_loc * 64 + h * 8 + p;
            float w  = sw [s];
            float px = spx[s];
            float py = spy[s];
            float x0f = floorf(px), y0f = floorf(py);
            float fx = px - x0f, fy = py - y0f;
            int x0 = (int)x0f, y0 = (int)y0f;

            bool xv0 = (x0 >= 0)  & (x0 < WDIM);
            bool xv1 = (x0 >= -1) & (x0 < WDIM - 1);
            bool yv0 = (y0 >= 0)  & (y0 < HDIM);
            bool yv1 = (y0 >= -1) & (y0 < HDIM - 1);

            float v00 = 0.f, v10 = 0.f, v01 = 0.f, v11 = 0.f;
            if (yv0) {
                int r = y0 * WDIM;
                if (xv0) v00 = vbase[(size_t)(r + x0)     * CHAN];
                if (xv1) v10 = vbase[(size_t)(r + x0 + 1) * CHAN];
            }
            if (yv1) {
                int r = (y0 + 1) * WDIM;
                if (xv0) v01 = vbase[(size_t)(r + x0)     * CHAN];
                if (xv1) v11 = vbase[(size_t)(r + x0 + 1) * CHAN];
            }
            float gx0 = 1.f - fx, gy0 = 1.f - fy;
            float bil = v00 * gx0 * gy0 + v10 * fx * gy0 + v01 * gx0 * fy + v11 * fx * fy;
            acc = fmaf(w, bil, acc);
        }
        g_mid[((size_t)b * LLEN + ly * WDIM + lx) * 128 + tt] = acc;
    }
}

// ---------------------------------------------------------------------------
// Kernel 3: output projection, 64l x 128n tile, 256 thr, 8n x 4l per thread.
// Transposed coalesced store: out[b, n, l].
// ---------------------------------------------------------------------------
__global__ __launch_bounds__(256)
void out_kernel(const float* __restrict__ Wout, const float* __restrict__ bout,
                float* __restrict__ out)
{
    __shared__ float As[64][17];      // [l][k], padded
    __shared__ float Bs[16][128];     // [k][n]

    const int b   = blockIdx.x >> 6;
    const int l0  = (blockIdx.x & 63) << 6;
    const int tid = threadIdx.x;
    const int tx  = tid & 15;         // -> l (strided 16)
    const int ty  = tid >> 4;         // -> 8 consecutive n

    float acc[8][4];
    #pragma unroll
    for (int i = 0; i < 8; i++)
        #pragma unroll
        for (int j = 0; j < 4; j++) acc[i][j] = 0.f;

    for (int k0 = 0; k0 < CHAN; k0 += 16) {
        {
            int row = tid >> 2, cg = (tid & 3) << 2;
            float4 v = *(const float4*)&g_mid[(size_t)(b * LLEN + l0 + row) * 128 + k0 + cg];
            As[row][cg] = v.x; As[row][cg + 1] = v.y;
            As[row][cg + 2] = v.z; As[row][cg + 3] = v.w;
        }
        #pragma unroll
        for (int i = 0; i < 2; i++) {
            int fid = tid + i * 256;
            int row = fid >> 5, c4 = (fid & 31) << 2;
            *(float4*)&Bs[row][c4] = *(const float4*)&Wout[(k0 + row) * 128 + c4];
        }
        __syncthreads();

        #pragma unroll
        for (int kk = 0; kk < 16; kk++) {
            float a[4];
            #pragma unroll
            for (int j = 0; j < 4; j++) a[j] = As[tx + 16 * j][kk];
            float4 w0 = *(float4*)&Bs[kk][ty * 8];
            float4 w1 = *(float4*)&Bs[kk][ty * 8 + 4];
            float wv[8] = {w0.x, w0.y, w0.z, w0.w, w1.x, w1.y, w1.z, w1.w};
            #pragma unroll
            for (int i = 0; i < 8; i++)
                #pragma unroll
                for (int j = 0; j < 4; j++)
                    acc[i][j] = fmaf(wv[i], a[j], acc[i][j]);
        }
        __syncthreads();
    }

    #pragma unroll
    for (int i = 0; i < 8; i++) {
        int n = ty * 8 + i;
        float bb = bout[n];
        #pragma unroll
        for (int j = 0; j < 4; j++) {
            out[((size_t)(b * CHAN + n)) * LLEN + l0 + tx + 16 * j] = acc[i][j] + bb;
        }
    }
}

// ---------------------------------------------------------------------------
extern "C" void kernel_launch(void* const* d_in, const int* in_sizes, int n_in,
                              void* d_out, int out_size)
{
    const float* nbr  = (const float*)d_in[0];
    const float* ext  = (const float*)d_in[1];
    const float* Wv   = (const float*)d_in[2];
    const float* bv   = (const float*)d_in[3];
    const float* Wo   = (const float*)d_in[4];
    const float* bo   = (const float*)d_in[5];
    const float* Wa   = (const float*)d_in[6];
    const float* ba   = (const float*)d_in[7];
    const float* Wout = (const float*)d_in[8];
    const float* bout = (const float*)d_in[9];
    float* out = (float*)d_out;

    dim3 gproj(256, 5);
    proj_kernel<<<gproj, 256>>>(nbr, ext, Wv, bv, Wo, bo, Wa, ba);

    dim3 gsamp(64, BATCH);
    sample_kernel<<<gsamp, 256>>>();

    out_kernel<<<512, 256>>>(Wout, bout, out);
}